// round 11
// baseline (speedup 1.0000x reference)
#include <cuda_runtime.h>

#define NT 512
#define CC 66
#define TT 100
#define JJ 22
#define HH 8
#define HD 64

// smem float offsets
#define OFF_SP   0        // sp   [66][100]   6600
#define OFF_TPT  6600     // tpT  [100][68]   6800
#define OFF_COMB 13400    // comb [104][68]   7072
#define OFF_W1   20472    // 4352
#define OFF_W2   24824    // 6400
#define OFF_W3   31224    // 6656
#define OFF_W4   37880    // 6400
#define OFF_STB  44280    // 7200
#define OFF_ASM  51480    // 484
#define OFF_RED  51964    // 832
#define SMEM_FLOATS 52796

__device__ __forceinline__ unsigned long long pk2(float lo, float hi) {
    unsigned long long r;
    asm("mov.b64 %0, {%1, %2};" : "=l"(r) : "f"(lo), "f"(hi));
    return r;
}
__device__ __forceinline__ void upk2(float& lo, float& hi, unsigned long long v) {
    asm("mov.b64 {%0, %1}, %2;" : "=f"(lo), "=f"(hi) : "l"(v));
}
__device__ __forceinline__ void fma2(unsigned long long& acc, unsigned long long a,
                                     unsigned long long b) {
    asm("fma.rn.f32x2 %0, %1, %2, %0;" : "+l"(acc) : "l"(a), "l"(b));
}

// C[m][n] (+)= scale * sum_k A[k][m]*B[k][n] (+ biasM[m] + biasN[n])
// 8x4 register tile, packed f32x2 FMA. Caller guarantees t < Mt*Nt.
// m-major lane mapping: a warp spans 8 m-tiles x 4 n-tiles -> B float4 is
// broadcast-deduped across lanes (unique bytes/warp/k: 8*32 + 4*16 = 320B).
__device__ __forceinline__ void gemm84(
    const float* __restrict__ A, const int lda,
    const float* __restrict__ B, const int ldb,
    float* __restrict__ C, const int ldc,
    const int Mt, const int K,
    const float* __restrict__ biasM, const float* __restrict__ biasN,
    const float scale, const bool accum, const int t)
{
    const int nt = t / Mt;
    const int mt = t - nt * Mt;
    const int m0 = mt << 3;
    const int n0 = nt << 2;

    unsigned long long acc[4][4];
    #pragma unroll
    for (int i = 0; i < 4; i++)
        #pragma unroll
        for (int j = 0; j < 4; j++) acc[i][j] = 0ull;

    const float* Ap = A + m0;
    const float* Bp = B + n0;
    #pragma unroll 2
    for (int k = 0; k < K; ++k) {
        const float4 a0 = *(const float4*)Ap;
        const float4 a1 = *(const float4*)(Ap + 4);
        const float4 bv = *(const float4*)Bp;
        Ap += lda; Bp += ldb;
        const unsigned long long ap0 = pk2(a0.x, a0.y);
        const unsigned long long ap1 = pk2(a0.z, a0.w);
        const unsigned long long ap2 = pk2(a1.x, a1.y);
        const unsigned long long ap3 = pk2(a1.z, a1.w);
        const unsigned long long b0 = pk2(bv.x, bv.x);
        const unsigned long long b1 = pk2(bv.y, bv.y);
        const unsigned long long b2 = pk2(bv.z, bv.z);
        const unsigned long long b3 = pk2(bv.w, bv.w);
        fma2(acc[0][0], ap0, b0); fma2(acc[1][0], ap1, b0);
        fma2(acc[2][0], ap2, b0); fma2(acc[3][0], ap3, b0);
        fma2(acc[0][1], ap0, b1); fma2(acc[1][1], ap1, b1);
        fma2(acc[2][1], ap2, b1); fma2(acc[3][1], ap3, b1);
        fma2(acc[0][2], ap0, b2); fma2(acc[1][2], ap1, b2);
        fma2(acc[2][2], ap2, b2); fma2(acc[3][2], ap3, b2);
        fma2(acc[0][3], ap0, b3); fma2(acc[1][3], ap1, b3);
        fma2(acc[2][3], ap2, b3); fma2(acc[3][3], ap3, b3);
    }

    float bn[4] = {0.f, 0.f, 0.f, 0.f};
    if (biasN) { bn[0] = biasN[n0]; bn[1] = biasN[n0+1]; bn[2] = biasN[n0+2]; bn[3] = biasN[n0+3]; }
    #pragma unroll
    for (int i2 = 0; i2 < 4; i2++) {
        float lo[4], hi[4];
        #pragma unroll
        for (int j = 0; j < 4; j++) upk2(lo[j], hi[j], acc[i2][j]);
        const int mA = m0 + (i2 << 1);
        float bmA = 0.f, bmB = 0.f;
        if (biasM) { bmA = biasM[mA]; bmB = biasM[mA + 1]; }
        float4 rA, rB;
        rA.x = fmaf(lo[0], scale, bmA + bn[0]);
        rA.y = fmaf(lo[1], scale, bmA + bn[1]);
        rA.z = fmaf(lo[2], scale, bmA + bn[2]);
        rA.w = fmaf(lo[3], scale, bmA + bn[3]);
        rB.x = fmaf(hi[0], scale, bmB + bn[0]);
        rB.y = fmaf(hi[1], scale, bmB + bn[1]);
        rB.z = fmaf(hi[2], scale, bmB + bn[2]);
        rB.w = fmaf(hi[3], scale, bmB + bn[3]);
        float* cA = C + mA * ldc + n0;
        float* cB = cA + ldc;
        if (accum) {
            const float4 oA = *(const float4*)cA;
            const float4 oB = *(const float4*)cB;
            rA.x += oA.x; rA.y += oA.y; rA.z += oA.z; rA.w += oA.w;
            rB.x += oB.x; rB.y += oB.y; rB.z += oB.z; rB.w += oB.w;
        }
        *(float4*)cA = rA;
        *(float4*)cB = rB;
    }
}

// stage [rows][64] head-slice of a [rows][512] weight matrix
__device__ __forceinline__ void stage_w(float* __restrict__ dst, const float* __restrict__ src,
                                        const int rows, const int ho, int i, const int n)
{
    const int total = rows << 6;
    for (; i < total; i += n)
        dst[i] = src[(i >> 6) * 512 + ho + (i & 63)];
}
// st_wo slice [64][66] -> dst[64][68], zero pad cols
__device__ __forceinline__ void stage_wo66(float* __restrict__ dst, const float* __restrict__ src,
                                           const int ho, int i, const int n)
{
    for (; i < 64 * 68; i += n) {
        const int d = i / 68, c = i - d * 68;
        dst[i] = (c < CC) ? src[(ho + d) * CC + c] : 0.f;
    }
}
// ts_wo slice [64][100] (contiguous)
__device__ __forceinline__ void stage_wo100(float* __restrict__ dst, const float* __restrict__ src,
                                            const int ho, int i, const int n)
{
    for (; i < 64 * TT; i += n) dst[i] = src[ho * TT + i];
}

// two-level softmax over rows (k) for each column q of M[k][q]. All NT threads enter.
__device__ __forceinline__ void softmax2(float* __restrict__ M, const int ld,
                                         const int R, const int Qn,
                                         float* __restrict__ red, const int tid)
{
    const int w = tid >> 5, l = tid & 31;
    const int chunk = w & 3;
    const int quarter = w >> 2;
    const int q = (chunk << 5) + l;
    const int rlo = (R * quarter) >> 2;
    const int rhi = (R * (quarter + 1)) >> 2;
    const bool act = (q < Qn);

    float mx = -1e30f;
    if (act) for (int r = rlo; r < rhi; r++) mx = fmaxf(mx, M[r * ld + q]);
    if (act) red[quarter * 104 + q] = mx;
    __syncthreads();
    float gm = 0.f;
    if (act) gm = fmaxf(fmaxf(red[q], red[104 + q]), fmaxf(red[208 + q], red[312 + q]));
    float s = 0.f;
    if (act) {
        for (int r = rlo; r < rhi; r++) {
            const float e = __expf(M[r * ld + q] - gm);
            M[r * ld + q] = e; s += e;
        }
    }
    __syncthreads();
    if (act) red[416 + quarter * 104 + q] = s;
    __syncthreads();
    if (act) {
        const float inv = 1.f / (red[416 + q] + red[520 + q] + red[624 + q] + red[728 + q]);
        for (int r = rlo; r < rhi; r++) M[r * ld + q] *= inv;
    }
}

__global__ __launch_bounds__(NT, 1)
void fused_kernel(
    const float* __restrict__ x,
    const float* __restrict__ adj_mask,
    const float* __restrict__ s_adj,
    const float* __restrict__ traj_mask,
    const float* __restrict__ t_adj,
    const float* __restrict__ st_wq, const float* __restrict__ st_bq,
    const float* __restrict__ st_wk, const float* __restrict__ st_bk,
    const float* __restrict__ st_wv, const float* __restrict__ st_bv,
    const float* __restrict__ st_wo, const float* __restrict__ st_bo,
    const float* __restrict__ ts_wq, const float* __restrict__ ts_bq,
    const float* __restrict__ ts_wk, const float* __restrict__ ts_bk,
    const float* __restrict__ ts_wv, const float* __restrict__ ts_bv,
    const float* __restrict__ ts_wo, const float* __restrict__ ts_bo,
    const float* __restrict__ ln_alpha, const float* __restrict__ ln_beta,
    const float* __restrict__ fc_w, const float* __restrict__ fc_b,
    float* __restrict__ out)
{
    extern __shared__ float S[];
    float* SP   = S + OFF_SP;
    float* TPT  = S + OFF_TPT;
    float* COMB = S + OFF_COMB;
    float* W1   = S + OFF_W1;
    float* W2   = S + OFF_W2;
    float* W3   = S + OFF_W3;
    float* W4   = S + OFF_W4;
    float* STB  = S + OFF_STB;
    float* ASM  = S + OFF_ASM;
    float* RED  = S + OFF_RED;

    const int b   = blockIdx.x;
    const int tid = threadIdx.x;
    const float* xb = x + (size_t)b * (CC * TT);

    // ================= phase 1 =================
    {
        float* xs = W1;            // [66][100]  scratch
        float* Ms = W1 + 6600;     // [100][100] scratch
        for (int i = tid; i < CC * TT; i += NT) xs[i] = xb[i];
        for (int i = tid; i < TT * TT; i += NT) Ms[i] = t_adj[i] * traj_mask[i];
        for (int i = tid; i < JJ * JJ; i += NT) {
            const int v = i / JJ, j = i % JJ;
            float dv = 0.f, dj = 0.f;
            for (int k = 0; k < JJ; k++) { dv += adj_mask[v * JJ + k]; dj += adj_mask[j * JJ + k]; }
            const float iv = dv > 0.f ? rsqrtf(dv) : 0.f;
            const float ij = dj > 0.f ? rsqrtf(dj) : 0.f;
            ASM[i] = s_adj[i] * adj_mask[i] * iv * ij;
        }
        __syncthreads();
        for (int i = tid; i < CC * TT; i += NT) {
            const int c = i / TT, t = i % TT;
            const int v = c / 3, dd = c % 3;
            float acc = 0.f;
            #pragma unroll
            for (int j = 0; j < JJ; j++)
                acc = fmaf(ASM[v * JJ + j], xs[(j * 3 + dd) * TT + t], acc);
            SP[i] = acc;
        }
        for (int i = tid; i < TT * 68; i += NT) {
            const int f = i / 68, c = i % 68;
            if (c >= CC) { TPT[i] = 0.f; continue; }
            const float4* mr = (const float4*)(Ms + f * TT);
            const float4* xr = (const float4*)(xs + c * TT);
            unsigned long long a01 = 0ull, a23 = 0ull;
            #pragma unroll 5
            for (int k = 0; k < TT / 4; k++) {
                const float4 m4 = mr[k], x4 = xr[k];
                fma2(a01, pk2(m4.x, m4.y), pk2(x4.x, x4.y));
                fma2(a23, pk2(m4.z, m4.w), pk2(x4.z, x4.w));
            }
            float l0, h0, l1, h1;
            upk2(l0, h0, a01); upk2(l1, h1, a23);
            TPT[i] = (l0 + h0) + (l1 + h1);
        }
        for (int i = tid; i < 104 * 68; i += NT) {
            const int t = i / 68, c = i % 68;
            COMB[i] = (t < TT && c < CC) ? (st_bo[c] + ts_bo[t]) : 0.f;
        }
        __syncthreads();
        // pre-stage wq_st(h0) -> W1, wk_st(h0) -> W3
        stage_w(W1, st_wq, CC, 0, tid, NT);
        stage_w(W3, st_wk, TT, 0, tid, NT);
        __syncthreads();
    }

    for (int h = 0; h < HH; h++) {
        const int ho  = h << 6;
        const int ho2 = ((h + 1) & 7) << 6;

        // S1: Q_st[d][t] -> W2 (M=64,N=100,K=66) | stage wv_st -> W4
        if (tid < 200)      gemm84(W1, 64, SP, 100, W2, 100, 8, CC, st_bq + ho, nullptr, 1.f, false, tid);
        else if (tid >= 224) stage_w(W4, st_wv, TT, ho, tid - 224, NT - 224);
        __syncthreads();
        // S2: K_st[d][c] -> W1 (M=64,N=66,K=100)  ||  V_st[c][d] -> STB (M=66,N=64,K=100)
        if (tid < 136)      gemm84(W3, 64, TPT, 68, W1, 68, 8, TT, st_bk + ho, nullptr, 1.f, false, tid);
        else if (tid >= 160 && tid < 304)
                            gemm84(TPT, 68, W4, 64, STB, 64, 9, TT, nullptr, st_bv + ho, 1.f, false, tid - 160);
        __syncthreads();
        // S3: scores_st[c][t] -> W3(+W4 spill) (M=66,N=100,K=64)
        if (tid < 225)      gemm84(W1, 68, W2, 100, W3, 100, 9, HD, nullptr, nullptr, 0.125f, false, tid);
        __syncthreads();
        // S4: softmax over c (66 rows), 100 cols
        softmax2(W3, 100, CC, TT, RED, tid);
        __syncthreads();
        // S5: O_st[d][t] -> W2 (M=64,N=100,K=66) | stage wo_st -> W1
        if (tid < 200)      gemm84(STB, 64, W3, 100, W2, 100, 8, CC, nullptr, nullptr, 1.f, false, tid);
        else if (tid >= 224) stage_wo66(W1, st_wo, ho, tid - 224, NT - 224);
        __syncthreads();
        // S6: COMB[t][c] += O^T Wo (M=100,N=66,K=64) | stage wq_ts -> W3, wk_ts -> STB
        if (tid < 221)      gemm84(W2, 100, W1, 68, COMB, 68, 13, HD, nullptr, nullptr, 1.f, true, tid);
        else if (tid >= 224) {
            for (int i = tid - 224; i < 6400 + 4224; i += NT - 224) {
                if (i < 6400) W3[i]  = ts_wq[(i >> 6) * 512 + ho + (i & 63)];
                else { const int j = i - 6400; STB[j] = ts_wk[(j >> 6) * 512 + ho + (j & 63)]; }
            }
        }
        __syncthreads();

        // T1: Q_ts[d][c] -> W1 (M=64,N=66,K=100) | stage wv_ts -> W4
        if (tid < 136)      gemm84(W3, 64, TPT, 68, W1, 68, 8, TT, ts_bq + ho, nullptr, 1.f, false, tid);
        else if (tid >= 160 && tid < 448) stage_w(W4, ts_wv, CC, ho, tid - 160, 288);
        __syncthreads();
        // T2: K_ts[d][t] -> W2 (M=64,N=100,K=66)  ||  V_ts[t][d] -> W3 (M=100,N=64,K=66)
        if (tid < 200)      gemm84(STB, 64, SP, 100, W2, 100, 8, CC, ts_bk + ho, nullptr, 1.f, false, tid);
        else if (tid >= 224 && tid < 432)
                            gemm84(SP, 100, W4, 64, W3, 64, 13, CC, nullptr, ts_bv + ho, 1.f, false, tid - 224);
        __syncthreads();
        // T3: scores_ts[t][c] -> STB (M=100,N=66,K=64) | stage wo_ts -> W4
        if (tid < 221)      gemm84(W2, 100, W1, 68, STB, 68, 13, HD, nullptr, nullptr, 0.125f, false, tid);
        else if (tid >= 256) stage_wo100(W4, ts_wo, ho, tid - 256, NT - 256);
        __syncthreads();
        // T4: softmax over t (100 rows), 66 cols
        softmax2(STB, 68, TT, CC, RED, tid);
        __syncthreads();
        // T5: O_ts[d][c] -> W2 (M=64,N=66,K=100) | stage next wq_st -> W1
        if (tid < 136)      gemm84(W3, 64, STB, 68, W2, 68, 8, TT, nullptr, nullptr, 1.f, false, tid);
        else if (tid >= 160 && tid < 448) stage_w(W1, st_wq, CC, ho2, tid - 160, 288);
        __syncthreads();
        // T6: COMB[t][c] += Wo^T O (M=100,N=66,K=64) | stage next wk_st -> W3
        if (tid < 221)      gemm84(W4, 100, W2, 68, COMB, 68, 13, HD, nullptr, nullptr, 1.f, true, tid);
        else if (tid >= 224) stage_w(W3, st_wk, TT, ho2, tid - 224, NT - 224);
        __syncthreads();
    }

    // ================= phase 3 =================
    {
        float* fw = W1;            // [100][100] spans W1..W2
        for (int i = tid; i < TT * TT; i += NT) fw[i] = fc_w[i];
        if (tid < TT) {
            const int t = tid;
            float mean = 0.f;
            for (int c = 0; c < CC; c++) mean += COMB[t * 68 + c];
            mean *= (1.f / 66.f);
            float var = 0.f;
            for (int c = 0; c < CC; c++) {
                const float v = COMB[t * 68 + c] - mean;
                var = fmaf(v, v, var);
            }
            var *= (1.f / 66.f);
            const float inv = rsqrtf(var + 1e-5f);
            for (int c = 0; c < CC; c++) {
                const float y = (COMB[t * 68 + c] - mean) * inv * ln_alpha[c] + ln_beta[c];
                SP[c * TT + t] = y + xb[c * TT + t];
            }
        }
        __syncthreads();
        float* outb = out + (size_t)b * (CC * TT);
        for (int i = tid; i < CC * TT; i += NT) {
            const int c = i / TT, f = i % TT;
            const float4* zr = (const float4*)(SP + c * TT);
            const float4* fr = (const float4*)(fw + f * TT);
            unsigned long long a01 = 0ull, a23 = 0ull;
            #pragma unroll 5
            for (int k = 0; k < TT / 4; k++) {
                const float4 z4 = zr[k], f4 = fr[k];
                fma2(a01, pk2(z4.x, z4.y), pk2(f4.x, f4.y));
                fma2(a23, pk2(z4.z, z4.w), pk2(f4.z, f4.w));
            }
            float l0, h0, l1, h1;
            upk2(l0, h0, a01); upk2(l1, h1, a23);
            outb[i] = tanhf(fc_b[f] + (l0 + h0) + (l1 + h1));
        }
    }
}

extern "C" void kernel_launch(void* const* d_in, const int* in_sizes, int n_in,
                              void* d_out, int out_size) {
    const float* x         = (const float*)d_in[0];
    const float* adj_mask  = (const float*)d_in[1];
    const float* s_adj     = (const float*)d_in[2];
    const float* traj_mask = (const float*)d_in[3];
    const float* t_adj     = (const float*)d_in[4];
    const float* st_wq = (const float*)d_in[5];  const float* st_bq = (const float*)d_in[6];
    const float* st_wk = (const float*)d_in[7];  const float* st_bk = (const float*)d_in[8];
    const float* st_wv = (const float*)d_in[9];  const float* st_bv = (const float*)d_in[10];
    const float* st_wo = (const float*)d_in[11]; const float* st_bo = (const float*)d_in[12];
    const float* ts_wq = (const float*)d_in[13]; const float* ts_bq = (const float*)d_in[14];
    const float* ts_wk = (const float*)d_in[15]; const float* ts_bk = (const float*)d_in[16];
    const float* ts_wv = (const float*)d_in[17]; const float* ts_bv = (const float*)d_in[18];
    const float* ts_wo = (const float*)d_in[19]; const float* ts_bo = (const float*)d_in[20];
    const float* ln_alpha = (const float*)d_in[21];
    const float* ln_beta  = (const float*)d_in[22];
    const float* fc_w     = (const float*)d_in[23];
    const float* fc_b     = (const float*)d_in[24];
    float* out = (float*)d_out;

    const int B = in_sizes[0] / (CC * TT);
    const size_t smem = (size_t)SMEM_FLOATS * sizeof(float);
    cudaFuncSetAttribute(fused_kernel, cudaFuncAttributeMaxDynamicSharedMemorySize, (int)smem);

    fused_kernel<<<B, NT, smem>>>(
        x, adj_mask, s_adj, traj_mask, t_adj,
        st_wq, st_bq, st_wk, st_bk, st_wv, st_bv, st_wo, st_bo,
        ts_wq, ts_bq, ts_wk, ts_bk, ts_wv, ts_bv, ts_wo, ts_bo,
        ln_alpha, ln_beta, fc_w, fc_b, out);
}

// round 12
// speedup vs baseline: 1.4859x; 1.4859x over previous
#include <cuda_runtime.h>

#define NT 512
#define CC 66
#define TT 100
#define JJ 22
#define HH 8
#define HD 64

// smem float offsets
#define OFF_SP   0        // sp   [66][100]            6600
#define OFF_TPT  6600     // tpT  [100][68]            6800
#define OFF_COMB 13400    // comb [100][68]            6800
#define OFF_RED  20200    // softmax partials / ASM    800
#define OFF_A    21000    // buf A                     4352
#define OFF_B    25352    // buf B                     6400
#define OFF_C    31752    // buf C                     6400
#define OFF_D    38152    // buf D                     6400
#define OFF_E    44552    // buf E                     6400
#define OFF_F    50952    // buf F                     6800
#define SMEM_FLOATS 57752

__device__ __forceinline__ unsigned long long pk2(float lo, float hi) {
    unsigned long long r;
    asm("mov.b64 %0, {%1, %2};" : "=l"(r) : "f"(lo), "f"(hi));
    return r;
}
__device__ __forceinline__ void upk2(float& lo, float& hi, unsigned long long v) {
    asm("mov.b64 {%0, %1}, %2;" : "=f"(lo), "=f"(hi) : "l"(v));
}
__device__ __forceinline__ void fma2(unsigned long long& acc, unsigned long long a,
                                     unsigned long long b) {
    asm("fma.rn.f32x2 %0, %1, %2, %0;" : "+l"(acc) : "l"(a), "l"(b));
}

// C[m][n] (+)= scale * sum_k A[k][m]*B[k][n] (+ biasM[m] + biasN[n])
// 8x4 register tile, packed f32x2 FMA, n-major lane map (R9-proven).
// Rows >= Mlim are clamped (not stored / not accumulated).
__device__ __forceinline__ void gemm84(
    const float* __restrict__ A, const int lda,
    const float* __restrict__ B, const int ldb,
    float* __restrict__ C, const int ldc,
    const int Nt, const int K, const int Mlim,
    const float* __restrict__ biasM, const float* __restrict__ biasN,
    const float scale, const bool accum, const int t)
{
    const int mt = t / Nt;
    const int m0 = mt << 3;
    const int n0 = (t - mt * Nt) << 2;

    unsigned long long acc[4][4];
    #pragma unroll
    for (int i = 0; i < 4; i++)
        #pragma unroll
        for (int j = 0; j < 4; j++) acc[i][j] = 0ull;

    const float* Ap = A + m0;
    const float* Bp = B + n0;
    #pragma unroll 2
    for (int k = 0; k < K; ++k) {
        const float4 a0 = *(const float4*)Ap;
        const float4 a1 = *(const float4*)(Ap + 4);
        const float4 bv = *(const float4*)Bp;
        Ap += lda; Bp += ldb;
        const unsigned long long ap0 = pk2(a0.x, a0.y);
        const unsigned long long ap1 = pk2(a0.z, a0.w);
        const unsigned long long ap2 = pk2(a1.x, a1.y);
        const unsigned long long ap3 = pk2(a1.z, a1.w);
        const unsigned long long b0 = pk2(bv.x, bv.x);
        const unsigned long long b1 = pk2(bv.y, bv.y);
        const unsigned long long b2 = pk2(bv.z, bv.z);
        const unsigned long long b3 = pk2(bv.w, bv.w);
        fma2(acc[0][0], ap0, b0); fma2(acc[1][0], ap1, b0);
        fma2(acc[2][0], ap2, b0); fma2(acc[3][0], ap3, b0);
        fma2(acc[0][1], ap0, b1); fma2(acc[1][1], ap1, b1);
        fma2(acc[2][1], ap2, b1); fma2(acc[3][1], ap3, b1);
        fma2(acc[0][2], ap0, b2); fma2(acc[1][2], ap1, b2);
        fma2(acc[2][2], ap2, b2); fma2(acc[3][2], ap3, b2);
        fma2(acc[0][3], ap0, b3); fma2(acc[1][3], ap1, b3);
        fma2(acc[2][3], ap2, b3); fma2(acc[3][3], ap3, b3);
    }

    float bn[4] = {0.f, 0.f, 0.f, 0.f};
    if (biasN) { bn[0] = biasN[n0]; bn[1] = biasN[n0+1]; bn[2] = biasN[n0+2]; bn[3] = biasN[n0+3]; }
    #pragma unroll
    for (int i2 = 0; i2 < 4; i2++) {
        const int mA = m0 + (i2 << 1);
        if (mA < Mlim) {
            float lo[4], hi[4];
            #pragma unroll
            for (int j = 0; j < 4; j++) upk2(lo[j], hi[j], acc[i2][j]);
            float bmA = 0.f, bmB = 0.f;
            if (biasM) { bmA = biasM[mA]; bmB = biasM[mA + 1]; }
            float4 rA, rB;
            rA.x = fmaf(lo[0], scale, bmA + bn[0]);
            rA.y = fmaf(lo[1], scale, bmA + bn[1]);
            rA.z = fmaf(lo[2], scale, bmA + bn[2]);
            rA.w = fmaf(lo[3], scale, bmA + bn[3]);
            rB.x = fmaf(hi[0], scale, bmB + bn[0]);
            rB.y = fmaf(hi[1], scale, bmB + bn[1]);
            rB.z = fmaf(hi[2], scale, bmB + bn[2]);
            rB.w = fmaf(hi[3], scale, bmB + bn[3]);
            float* cA = C + mA * ldc + n0;
            float* cB = cA + ldc;
            if (accum) {
                const float4 oA = *(const float4*)cA;
                rA.x += oA.x; rA.y += oA.y; rA.z += oA.z; rA.w += oA.w;
            }
            *(float4*)cA = rA;
            if (mA + 1 < Mlim) {
                if (accum) {
                    const float4 oB = *(const float4*)cB;
                    rB.x += oB.x; rB.y += oB.y; rB.z += oB.z; rB.w += oB.w;
                }
                *(float4*)cB = rB;
            }
        }
    }
}

// stage [rows][64] head-slice of a [rows][512] weight matrix
__device__ __forceinline__ void stage_w(float* __restrict__ dst, const float* __restrict__ src,
                                        const int rows, const int ho, int i, const int n)
{
    const int total = rows << 6;
    for (; i < total; i += n)
        dst[i] = src[(i >> 6) * 512 + ho + (i & 63)];
}
// st_wo slice [64][66] -> dst[64][68], zero pad cols
__device__ __forceinline__ void stage_wo66(float* __restrict__ dst, const float* __restrict__ src,
                                           const int ho, int i, const int n)
{
    for (; i < 64 * 68; i += n) {
        const int d = i / 68, c = i - d * 68;
        dst[i] = (c < CC) ? src[(ho + d) * CC + c] : 0.f;
    }
}
// ts_wo slice [64][100] (contiguous)
__device__ __forceinline__ void stage_wo100(float* __restrict__ dst, const float* __restrict__ src,
                                            const int ho, int i, const int n)
{
    for (; i < 64 * TT; i += n) dst[i] = src[ho * TT + i];
}

// two-level softmax over rows (k) for each column q of M[k][q]. All NT threads enter.
// red layout: max at [quarter*100 + q], sum at [400 + quarter*100 + q]  (q < 100)
__device__ __forceinline__ void softmax2(float* __restrict__ M, const int ld,
                                         const int R, const int Qn,
                                         float* __restrict__ red, const int tid)
{
    const int w = tid >> 5, l = tid & 31;
    const int chunk = w & 3;
    const int quarter = w >> 2;
    const int q = (chunk << 5) + l;
    const int rlo = (R * quarter) >> 2;
    const int rhi = (R * (quarter + 1)) >> 2;
    const bool act = (q < Qn);

    float mx = -1e30f;
    if (act) for (int r = rlo; r < rhi; r++) mx = fmaxf(mx, M[r * ld + q]);
    if (act) red[quarter * 100 + q] = mx;
    __syncthreads();
    float gm = 0.f;
    if (act) gm = fmaxf(fmaxf(red[q], red[100 + q]), fmaxf(red[200 + q], red[300 + q]));
    float s = 0.f;
    if (act) {
        for (int r = rlo; r < rhi; r++) {
            const float e = __expf(M[r * ld + q] - gm);
            M[r * ld + q] = e; s += e;
        }
    }
    __syncthreads();
    if (act) red[400 + quarter * 100 + q] = s;
    __syncthreads();
    if (act) {
        const float inv = 1.f / (red[400 + q] + red[500 + q] + red[600 + q] + red[700 + q]);
        for (int r = rlo; r < rhi; r++) M[r * ld + q] *= inv;
    }
}

__global__ __launch_bounds__(NT, 1)
void fused_kernel(
    const float* __restrict__ x,
    const float* __restrict__ adj_mask,
    const float* __restrict__ s_adj,
    const float* __restrict__ traj_mask,
    const float* __restrict__ t_adj,
    const float* __restrict__ st_wq, const float* __restrict__ st_bq,
    const float* __restrict__ st_wk, const float* __restrict__ st_bk,
    const float* __restrict__ st_wv, const float* __restrict__ st_bv,
    const float* __restrict__ st_wo, const float* __restrict__ st_bo,
    const float* __restrict__ ts_wq, const float* __restrict__ ts_bq,
    const float* __restrict__ ts_wk, const float* __restrict__ ts_bk,
    const float* __restrict__ ts_wv, const float* __restrict__ ts_bv,
    const float* __restrict__ ts_wo, const float* __restrict__ ts_bo,
    const float* __restrict__ ln_alpha, const float* __restrict__ ln_beta,
    const float* __restrict__ fc_w, const float* __restrict__ fc_b,
    float* __restrict__ out)
{
    extern __shared__ float S[];
    float* SP   = S + OFF_SP;
    float* TPT  = S + OFF_TPT;
    float* COMB = S + OFF_COMB;
    float* RED  = S + OFF_RED;   // also ASM in phase 1
    float* BA   = S + OFF_A;
    float* BB   = S + OFF_B;
    float* BC   = S + OFF_C;
    float* BD   = S + OFF_D;
    float* BE   = S + OFF_E;
    float* BF   = S + OFF_F;

    const int b   = blockIdx.x;
    const int tid = threadIdx.x;
    const float* xb = x + (size_t)b * (CC * TT);

    // ================= phase 1 =================
    {
        float* ASM = RED;          // [22][22] (484 <= 800)
        float* xs  = BA;           // [66][100] scratch (spans A..B)
        float* Ms  = BA + 6600;    // [100][100] scratch (spans B..D)
        for (int i = tid; i < CC * TT; i += NT) xs[i] = xb[i];
        for (int i = tid; i < TT * TT; i += NT) Ms[i] = t_adj[i] * traj_mask[i];
        for (int i = tid; i < JJ * JJ; i += NT) {
            const int v = i / JJ, j = i % JJ;
            float dv = 0.f, dj = 0.f;
            for (int k = 0; k < JJ; k++) { dv += adj_mask[v * JJ + k]; dj += adj_mask[j * JJ + k]; }
            const float iv = dv > 0.f ? rsqrtf(dv) : 0.f;
            const float ij = dj > 0.f ? rsqrtf(dj) : 0.f;
            ASM[i] = s_adj[i] * adj_mask[i] * iv * ij;
        }
        __syncthreads();
        for (int i = tid; i < CC * TT; i += NT) {
            const int c = i / TT, t = i % TT;
            const int v = c / 3, dd = c % 3;
            float acc = 0.f;
            #pragma unroll
            for (int j = 0; j < JJ; j++)
                acc = fmaf(ASM[v * JJ + j], xs[(j * 3 + dd) * TT + t], acc);
            SP[i] = acc;
        }
        for (int i = tid; i < TT * 68; i += NT) {
            const int f = i / 68, c = i % 68;
            if (c >= CC) { TPT[i] = 0.f; continue; }
            const float4* mr = (const float4*)(Ms + f * TT);
            const float4* xr = (const float4*)(xs + c * TT);
            unsigned long long a01 = 0ull, a23 = 0ull;
            #pragma unroll 5
            for (int k = 0; k < TT / 4; k++) {
                const float4 m4 = mr[k], x4 = xr[k];
                fma2(a01, pk2(m4.x, m4.y), pk2(x4.x, x4.y));
                fma2(a23, pk2(m4.z, m4.w), pk2(x4.z, x4.w));
            }
            float l0, h0, l1, h1;
            upk2(l0, h0, a01); upk2(l1, h1, a23);
            TPT[i] = (l0 + h0) + (l1 + h1);
        }
        for (int i = tid; i < TT * 68; i += NT) {
            const int t = i / 68, c = i % 68;
            COMB[i] = (c < CC) ? (st_bo[c] + ts_bo[t]) : 0.f;
        }
        __syncthreads();
        // pre-stage head0: wq_st -> A, wk_st -> B
        stage_w(BA, st_wq, CC, 0, tid, NT);
        stage_w(BB, st_wk, TT, 0, tid, NT);
        __syncthreads();
    }

    for (int h = 0; h < HH; h++) {
        const int ho  = h << 6;
        const int ho2 = ((h + 1) & 7) << 6;

        // M1: Q_st = A(wq) x SP -> C [64][100]   (200t, warps 0-6)
        //     K_st = B(wk) x TPT -> D [64][68]   (136t, warps 7-11)
        //     stage wv_st -> E                   (warps 12-15)
        if (tid < 200)       gemm84(BA, 64, SP, 100, BC, 100, 25, CC, 64, st_bq + ho, nullptr, 1.f, false, tid);
        else if (tid >= 224 && tid < 360)
                             gemm84(BB, 64, TPT, 68, BD, 68, 17, TT, 64, st_bk + ho, nullptr, 1.f, false, tid - 224);
        else if (tid >= 384) stage_w(BE, st_wv, TT, ho, tid - 384, 128);
        __syncthreads();
        // M2: scores_st = D(K) x C(Q) -> F [66][100]  (225t, warps 0-7, Mlim=66)
        //     V_st = TPT x E(wv) -> B [66][64]        (144t, warps 8-12, Mlim=66)
        //     stage wo_st -> A                        (warps 13-15)
        if (tid < 225)       gemm84(BD, 68, BC, 100, BF, 100, 25, HD, 66, nullptr, nullptr, 0.125f, false, tid);
        else if (tid >= 256 && tid < 400)
                             gemm84(TPT, 68, BE, 64, BB, 64, 16, TT, 66, nullptr, st_bv + ho, 1.f, false, tid - 256);
        else if (tid >= 416) stage_wo66(BA, st_wo, ho, tid - 416, 96);
        __syncthreads();
        // M3: softmax over c (66 rows), 100 cols
        softmax2(BF, 100, CC, TT, RED, tid);
        __syncthreads();
        // M4: O_st = B(V) x F(P) -> C [64][100]  (200t, warps 0-6)
        //     stage wq_ts -> D, wk_ts -> E       (warps 7-15, 288t)
        if (tid < 200)       gemm84(BB, 64, BF, 100, BC, 100, 25, CC, 64, nullptr, nullptr, 1.f, false, tid);
        else if (tid >= 224) {
            for (int i = tid - 224; i < 6400 + 4224; i += 288) {
                if (i < 6400) BD[i] = ts_wq[(i >> 6) * 512 + ho + (i & 63)];
                else { const int j = i - 6400; BE[j] = ts_wk[(j >> 6) * 512 + ho + (j & 63)]; }
            }
        }
        __syncthreads();
        // M5: COMB[t][c] += C(O)^T x A(wo)  (221t, warps 0-6, Mlim=100)
        //     stage wv_ts -> B               (warps 7-15, 288t)
        if (tid < 221)       gemm84(BC, 100, BA, 68, COMB, 68, 17, HD, 100, nullptr, nullptr, 1.f, true, tid);
        else if (tid >= 224) stage_w(BB, ts_wv, CC, ho, tid - 224, 288);
        __syncthreads();
        // M6: Q_ts = D(wq_ts) x TPT -> A [64][68]   (136t, warps 0-4)
        //     K_ts = E(wk_ts) x SP -> C [64][100]   (200t, warps 5-11)
        if (tid < 136)       gemm84(BD, 64, TPT, 68, BA, 68, 17, TT, 64, ts_bq + ho, nullptr, 1.f, false, tid);
        else if (tid >= 160 && tid < 360)
                             gemm84(BE, 64, SP, 100, BC, 100, 25, CC, 64, ts_bk + ho, nullptr, 1.f, false, tid - 160);
        __syncthreads();
        // M7: scores_ts = C(Kts) x A(Qts) -> F [100][68]  (221t, warps 0-6, Mlim=100)
        //     V_ts = SP x B(wv_ts) -> E [100][64]         (208t, warps 7-13, Mlim=100)
        //     stage wo_ts -> D                            (warps 14-15, 64t)
        if (tid < 221)       gemm84(BC, 100, BA, 68, BF, 68, 17, HD, 100, nullptr, nullptr, 0.125f, false, tid);
        else if (tid >= 224 && tid < 432)
                             gemm84(SP, 100, BB, 64, BE, 64, 16, CC, 100, nullptr, ts_bv + ho, 1.f, false, tid - 224);
        else if (tid >= 448) stage_wo100(BD, ts_wo, ho, tid - 448, 64);
        __syncthreads();
        // M8: softmax over t (100 rows), 66 cols
        softmax2(BF, 68, TT, CC, RED, tid);
        __syncthreads();
        // M9: O_ts = E(Vts) x F(P) -> C [64][68]  (136t, warps 0-4)
        //     stage next wq_st -> A, wk_st -> B   (warps 5-15, 352t)
        if (tid < 136)       gemm84(BE, 64, BF, 68, BC, 68, 17, TT, 64, nullptr, nullptr, 1.f, false, tid);
        else if (tid >= 160) {
            for (int i = tid - 160; i < 4224 + 6400; i += 352) {
                if (i < 4224) BA[i] = st_wq[(i >> 6) * 512 + ho2 + (i & 63)];
                else { const int j = i - 4224; BB[j] = st_wk[(j >> 6) * 512 + ho2 + (j & 63)]; }
            }
        }
        __syncthreads();
        // M10: COMB[t][c] += D(wo_ts)^T x C(Ots)  (221t, warps 0-6, Mlim=100)
        if (tid < 221)       gemm84(BD, 100, BC, 68, COMB, 68, 17, HD, 100, nullptr, nullptr, 1.f, true, tid);
        __syncthreads();
    }

    // ================= phase 3 =================
    {
        float* fw = BA;            // [100][100] spans A..C
        for (int i = tid; i < TT * TT; i += NT) fw[i] = fc_w[i];
        if (tid < TT) {
            const int t = tid;
            float mean = 0.f;
            for (int c = 0; c < CC; c++) mean += COMB[t * 68 + c];
            mean *= (1.f / 66.f);
            float var = 0.f;
            for (int c = 0; c < CC; c++) {
                const float v = COMB[t * 68 + c] - mean;
                var = fmaf(v, v, var);
            }
            var *= (1.f / 66.f);
            const float inv = rsqrtf(var + 1e-5f);
            for (int c = 0; c < CC; c++) {
                const float y = (COMB[t * 68 + c] - mean) * inv * ln_alpha[c] + ln_beta[c];
                SP[c * TT + t] = y + xb[c * TT + t];
            }
        }
        __syncthreads();
        float* outb = out + (size_t)b * (CC * TT);
        for (int i = tid; i < CC * TT; i += NT) {
            const int c = i / TT, f = i % TT;
            const float4* zr = (const float4*)(SP + c * TT);
            const float4* fr = (const float4*)(fw + f * TT);
            unsigned long long a01 = 0ull, a23 = 0ull;
            #pragma unroll 5
            for (int k = 0; k < TT / 4; k++) {
                const float4 z4 = zr[k], f4 = fr[k];
                fma2(a01, pk2(z4.x, z4.y), pk2(f4.x, f4.y));
                fma2(a23, pk2(z4.z, z4.w), pk2(f4.z, f4.w));
            }
            float l0, h0, l1, h1;
            upk2(l0, h0, a01); upk2(l1, h1, a23);
            outb[i] = tanhf(fc_b[f] + (l0 + h0) + (l1 + h1));
        }
    }
}

extern "C" void kernel_launch(void* const* d_in, const int* in_sizes, int n_in,
                              void* d_out, int out_size) {
    const float* x         = (const float*)d_in[0];
    const float* adj_mask  = (const float*)d_in[1];
    const float* s_adj     = (const float*)d_in[2];
    const float* traj_mask = (const float*)d_in[3];
    const float* t_adj     = (const float*)d_in[4];
    const float* st_wq = (const float*)d_in[5];  const float* st_bq = (const float*)d_in[6];
    const float* st_wk = (const float*)d_in[7];  const float* st_bk = (const float*)d_in[8];
    const float* st_wv = (const float*)d_in[9];  const float* st_bv = (const float*)d_in[10];
    const float* st_wo = (const float*)d_in[11]; const float* st_bo = (const float*)d_in[12];
    const float* ts_wq = (const float*)d_in[13]; const float* ts_bq = (const float*)d_in[14];
    const float* ts_wk = (const float*)d_in[15]; const float* ts_bk = (const float*)d_in[16];
    const float* ts_wv = (const float*)d_in[17]; const float* ts_bv = (const float*)d_in[18];
    const float* ts_wo = (const float*)d_in[19]; const float* ts_bo = (const float*)d_in[20];
    const float* ln_alpha = (const float*)d_in[21];
    const float* ln_beta  = (const float*)d_in[22];
    const float* fc_w     = (const float*)d_in[23];
    const float* fc_b     = (const float*)d_in[24];
    float* out = (float*)d_out;

    const int B = in_sizes[0] / (CC * TT);
    const size_t smem = (size_t)SMEM_FLOATS * sizeof(float);
    cudaFuncSetAttribute(fused_kernel, cudaFuncAttributeMaxDynamicSharedMemorySize, (int)smem);

    fused_kernel<<<B, NT, smem>>>(
        x, adj_mask, s_adj, traj_mask, t_adj,
        st_wq, st_bq, st_wk, st_bk, st_wv, st_bv, st_wo, st_bo,
        ts_wq, ts_bq, ts_wk, ts_bk, ts_wv, ts_bv, ts_wo, ts_bo,
        ln_alpha, ln_beta, fc_w, fc_b, out);
}